// round 1
// baseline (speedup 1.0000x reference)
#include <cuda_runtime.h>
#include <cstdint>

// CIC deposition: 10M particles -> 256^3 float grid.
// Reference semantics: fi=(p-GRID_MIN)/DX, i0=floor(fi), padded idx=i0+1,
// mask 1<=idx<=256 (i.e. i0 in [0,255]), scatter 8 trilinear corners into
// padded 258^3, crop [1:-1]. Cropped coords: c=i0, corner c+o kept iff <=255.

static constexpr int   NC    = 256;
static constexpr float GMINF = -10.0f;
// DX computed in double like the Python reference, then used as float32
static constexpr float DXF   = (float)(20.0 / 255.0);

__global__ void zero_grid_kernel(float4* __restrict__ out, int n4) {
    int i = blockIdx.x * blockDim.x + threadIdx.x;
    if (i < n4) out[i] = make_float4(0.f, 0.f, 0.f, 0.f);
}

__global__ void __launch_bounds__(256) cic_deposit_kernel(
    const float* __restrict__ pos,
    const float* __restrict__ wgt,
    float* __restrict__ grid,
    int n)
{
    int i = blockIdx.x * blockDim.x + threadIdx.x;
    if (i >= n) return;

    // Coalesced-ish: warp reads 384 contiguous bytes of positions
    float px = pos[3 * i + 0];
    float py = pos[3 * i + 1];
    float pz = pos[3 * i + 2];
    float w  = wgt[i];

    // Match JAX float32 arithmetic exactly: subtract then IEEE divide
    float fx = (px - GMINF) / DXF;
    float fy = (py - GMINF) / DXF;
    float fz = (pz - GMINF) / DXF;

    float ix = floorf(fx), iy = floorf(fy), iz = floorf(fz);
    int cx = (int)ix, cy = (int)iy, cz = (int)iz;

    // in-grid mask (reference: 1 <= idx <= 256  <=>  0 <= i0 <= 255)
    if ((unsigned)cx > 255u || (unsigned)cy > 255u || (unsigned)cz > 255u) return;

    float ox = fx - ix, oy = fy - iy, oz = fz - iz;

    // corner weight = ((w * Xterm) * Yterm) * Zterm  (reference association)
    float wx0 = w * (1.0f - ox);
    float wx1 = w * ox;
    float y0 = 1.0f - oy, y1 = oy;
    float z0 = 1.0f - oz, z1 = oz;

    bool bx = cx < (NC - 1);
    bool by = cy < (NC - 1);
    bool bz = cz < (NC - 1);

    float* g = grid + (((size_t)cx * NC + (size_t)cy) * NC + (size_t)cz);
    const size_t SX = (size_t)NC * NC;  // 65536
    const size_t SY = NC;               // 256

    // x = cx plane
    atomicAdd(g,                 wx0 * y0 * z0);
    if (bz) atomicAdd(g + 1,     wx0 * y0 * z1);
    if (by) {
        atomicAdd(g + SY,        wx0 * y1 * z0);
        if (bz) atomicAdd(g + SY + 1, wx0 * y1 * z1);
    }
    // x = cx+1 plane
    if (bx) {
        float* gx = g + SX;
        atomicAdd(gx,                 wx1 * y0 * z0);
        if (bz) atomicAdd(gx + 1,     wx1 * y0 * z1);
        if (by) {
            atomicAdd(gx + SY,        wx1 * y1 * z0);
            if (bz) atomicAdd(gx + SY + 1, wx1 * y1 * z1);
        }
    }
}

extern "C" void kernel_launch(void* const* d_in, const int* in_sizes, int n_in,
                              void* d_out, int out_size) {
    const float* positions = (const float*)d_in[0];
    const float* weights   = (const float*)d_in[1];
    float* grid = (float*)d_out;

    int n_particles = in_sizes[1];  // weights element count = N

    // 1) zero the output grid (d_out is poisoned before timing)
    int n4 = out_size / 4;  // 16777216 floats -> 4194304 float4
    zero_grid_kernel<<<(n4 + 255) / 256, 256>>>((float4*)grid, n4);

    // 2) deposit
    int threads = 256;
    int blocks = (n_particles + threads - 1) / threads;
    cic_deposit_kernel<<<blocks, threads>>>(positions, weights, grid, n_particles);
}

// round 2
// speedup vs baseline: 1.5103x; 1.5103x over previous
#include <cuda_runtime.h>
#include <cstdint>

// CIC deposition: 10M particles -> 256^3 float grid.
// Round 2: replace pairs of scalar atomics on adjacent z-cells with a single
// predicated red.global.add.v4.f32 when the (cz, cz+1) pair sits inside one
// 16B-aligned quad (cz % 4 != 3, ~75% of particles). Branchless lane build.

static constexpr int   NC    = 256;
static constexpr float GMINF = -10.0f;
static constexpr float DXF   = (float)(20.0 / 255.0);

__global__ void zero_grid_kernel(float4* __restrict__ out, int n4) {
    int i = blockIdx.x * blockDim.x + threadIdx.x;
    if (i < n4) out[i] = make_float4(0.f, 0.f, 0.f, 0.f);
}

__device__ __forceinline__ void red_v4p(float* p, float a, float b, float c, float d, int pred) {
    asm volatile(
        "{\n\t"
        ".reg .pred q;\n\t"
        "setp.ne.s32 q, %5, 0;\n\t"
        "@q red.global.add.v4.f32 [%0], {%1, %2, %3, %4};\n\t"
        "}"
        :: "l"(p), "f"(a), "f"(b), "f"(c), "f"(d), "r"(pred) : "memory");
}

__device__ __forceinline__ void red_v1p(float* p, float a, int pred) {
    asm volatile(
        "{\n\t"
        ".reg .pred q;\n\t"
        "setp.ne.s32 q, %2, 0;\n\t"
        "@q red.global.add.f32 [%0], %1;\n\t"
        "}"
        :: "l"(p), "f"(a), "r"(pred) : "memory");
}

__global__ void __launch_bounds__(256) cic_deposit_kernel(
    const float* __restrict__ pos,
    const float* __restrict__ wgt,
    float* __restrict__ grid,
    int n)
{
    int i = blockIdx.x * blockDim.x + threadIdx.x;
    if (i >= n) return;

    float px = pos[3 * i + 0];
    float py = pos[3 * i + 1];
    float pz = pos[3 * i + 2];
    float w  = wgt[i];

    // Match JAX float32 arithmetic: subtract then IEEE divide
    float fx = (px - GMINF) / DXF;
    float fy = (py - GMINF) / DXF;
    float fz = (pz - GMINF) / DXF;

    float ix = floorf(fx), iy = floorf(fy), iz = floorf(fz);
    int cx = (int)ix, cy = (int)iy, cz = (int)iz;

    // in-grid mask (reference: 0 <= i0 <= 255 in every dim)
    if ((unsigned)cx > 255u || (unsigned)cy > 255u || (unsigned)cz > 255u) return;

    float ox = fx - ix, oy = fy - iy, oz = fz - iz;

    // corner weight = ((w * Xterm) * Yterm) * Zterm (reference association)
    float wx0 = w * (1.0f - ox);
    float wx1 = w * ox;
    float y0 = 1.0f - oy, y1 = oy;
    float z0 = 1.0f - oz, z1 = oz;

    bool bx = cx < (NC - 1);
    bool by = cy < (NC - 1);

    // z-pair vectorization setup (shared across all 4 rows)
    int  m       = cz & 3;                 // position of cz within aligned quad
    int  use4    = (m != 3);               // pair fits in one 16B quad (also cz<255)
    int  fb      = !use4;                  // fallback: scalar red(s)
    int  fb2     = fb & (cz < (NC - 1));   // second scalar only if cz+1 in grid
    // 0/1 lane masks as floats: lane L receives v0*aL + v1*a(L-1)
    float a0 = (m == 0) ? 1.0f : 0.0f;
    float a1 = (m == 1) ? 1.0f : 0.0f;
    float a2 = (m == 2) ? 1.0f : 0.0f;

    float* g = grid + (((size_t)cx * NC + (size_t)cy) * NC + (size_t)cz);
    float* gq = g - m;                      // 16B-aligned quad base
    const size_t SX = (size_t)NC * NC;
    const size_t SY = NC;

    // one row = contributions (v0 at cz, v1 at cz+1)
    #define DEPOSIT_ROW(base_off, rw)  do {                                   \
        float v0 = (rw) * z0;                                                 \
        float v1 = (rw) * z1;                                                 \
        float l0 = v0 * a0;                                                   \
        float l1 = fmaf(v1, a0, v0 * a1);                                     \
        float l2 = fmaf(v1, a1, v0 * a2);                                     \
        float l3 = v1 * a2;                                                   \
        red_v4p(gq + (base_off), l0, l1, l2, l3, use4);                       \
        red_v1p(g + (base_off), v0, fb);                                      \
        red_v1p(g + (base_off) + 1, v1, fb2);                                 \
    } while (0)

    // x = cx plane
    DEPOSIT_ROW(0, wx0 * y0);
    if (by) DEPOSIT_ROW(SY, wx0 * y1);
    // x = cx+1 plane
    if (bx) {
        DEPOSIT_ROW(SX, wx1 * y0);
        if (by) DEPOSIT_ROW(SX + SY, wx1 * y1);
    }
    #undef DEPOSIT_ROW
}

extern "C" void kernel_launch(void* const* d_in, const int* in_sizes, int n_in,
                              void* d_out, int out_size) {
    const float* positions = (const float*)d_in[0];
    const float* weights   = (const float*)d_in[1];
    float* grid = (float*)d_out;

    int n_particles = in_sizes[1];  // weights element count = N

    int n4 = out_size / 4;
    zero_grid_kernel<<<(n4 + 255) / 256, 256>>>((float4*)grid, n4);

    int threads = 256;
    int blocks = (n_particles + threads - 1) / threads;
    cic_deposit_kernel<<<blocks, threads>>>(positions, weights, grid, n_particles);
}